// round 12
// baseline (speedup 1.0000x reference)
#include <cuda_runtime.h>
#include <cuda_bf16.h>
#include <math.h>
#include <stdint.h>

#define BATCH 4
#define HH 128
#define WW 128
#define HW (HH*WW)

// ---- scratch (static device globals; no allocation allowed) ----
// packed bf16x2 channel-pair planes (word cp = channels 2cp,2cp+1)
__device__ uint32_t g_xin_hi[BATCH*65*HW], g_xin_lo[BATCH*65*HW];  // conv1 input (65 pairs)
__device__ uint32_t g_hA_hi [BATCH*32*HW], g_hA_lo [BATCH*32*HW];
__device__ uint32_t g_hB_hi [BATCH*32*HW], g_hB_lo [BATCH*32*HW];
__device__ float    g_om[BATCH*432*HW];   // conv4 out: offsets+mask (fp32 for deform)
// pre-converted weights, layout [g][tap][coutPad][kp]
__device__ uint32_t g_w1_hi[9*9*64*8],  g_w1_lo[9*9*64*8];
__device__ uint32_t g_w2_hi[4*9*64*8],  g_w2_lo[4*9*64*8];
__device__ uint32_t g_w3_hi[4*9*64*8],  g_w3_lo[4*9*64*8];
__device__ uint32_t g_w4_hi[4*9*448*8], g_w4_lo[4*9*448*8];
// deform weights: [g][cout 64][kp 24] (k = tap*4+cg, 36 real -> 48 padded)
__device__ uint32_t g_dw_hi[16*64*24], g_dw_lo[16*64*24];

__device__ __forceinline__ uint32_t* xbuf_hi(int i) {
    switch (i) { case 0: return g_xin_hi; case 1: return g_hA_hi; default: return g_hB_hi; }
}
__device__ __forceinline__ uint32_t* xbuf_lo(int i) {
    switch (i) { case 0: return g_xin_lo; case 1: return g_hA_lo; default: return g_hB_lo; }
}
__device__ __forceinline__ uint32_t* wbuf(int i, int lo) {
    switch (i) {
        case 1: return lo ? g_w1_lo : g_w1_hi;
        case 2: return lo ? g_w2_lo : g_w2_hi;
        case 3: return lo ? g_w3_lo : g_w3_hi;
        default: return lo ? g_w4_lo : g_w4_hi;
    }
}

__device__ __forceinline__ uint32_t packbf2(float a, float b) {
    __nv_bfloat162 h = __floats2bfloat162_rn(a, b);
    return *reinterpret_cast<uint32_t*>(&h);
}
__device__ __forceinline__ float bf16r(float v) {
    return __bfloat162float(__float2bfloat16_rn(v));
}

// =====================================================================
// prep kernels (tiny, run once per launch inside the graph)
// =====================================================================
__global__ void prep_in_k(const float* __restrict__ xfw,
                          const float* __restrict__ xc,
                          const float* __restrict__ fl)
{
    int i = blockIdx.x * 256 + threadIdx.x;
    const int total = BATCH * 65 * HW;
    if (i >= total) return;
    int b  = i / (65 * HW);
    int r  = i - b * 65 * HW;
    int cp = r / HW;
    int sp = r - cp * HW;
    float v0, v1;
    if (cp < 32) {
        const float* s = xfw + ((size_t)b * 64 + 2 * cp) * HW + sp;
        v0 = s[0]; v1 = s[HW];
    } else if (cp < 64) {
        const float* s = xc + ((size_t)b * 64 + 2 * (cp - 32)) * HW + sp;
        v0 = s[0]; v1 = s[HW];
    } else {
        const float* s = fl + (size_t)b * 2 * HW + sp;
        v0 = s[0]; v1 = s[HW];
    }
    float h0 = bf16r(v0), h1 = bf16r(v1);
    g_xin_hi[i] = packbf2(h0, h1);
    g_xin_lo[i] = packbf2(v0 - h0, v1 - h1);
}

__global__ void prep_w_k(const float* __restrict__ wt,
                         int CinR, int CoutPad, int CoutReal, int nG, int wsel)
{
    int i = blockIdx.x * 256 + threadIdx.x;
    const int total = nG * 9 * CoutPad * 8;
    if (i >= total) return;
    int kp  = i & 7;
    int n   = (i >> 3) % CoutPad;
    int tap = ((i >> 3) / CoutPad) % 9;
    int g   = i / (9 * CoutPad * 8);
    int cin = g * 16 + kp * 2;
    float w0 = 0.f, w1 = 0.f;
    if (n < CoutReal) {
        if (cin     < CinR) w0 = wt[((size_t)n * CinR + cin    ) * 9 + tap];
        if (cin + 1 < CinR) w1 = wt[((size_t)n * CinR + cin + 1) * 9 + tap];
    }
    float h0 = bf16r(w0), h1 = bf16r(w1);
    wbuf(wsel, 0)[i] = packbf2(h0, h1);
    wbuf(wsel, 1)[i] = packbf2(w0 - h0, w1 - h1);
}

// deform weights: k-index = tap*4 + cg; kp pairs (0..17 real, 18..23 zero)
__global__ void prep_dw_k(const float* __restrict__ wt)
{
    int i = blockIdx.x * 256 + threadIdx.x;
    if (i >= 16 * 64 * 24) return;
    int kp = i % 24;
    int n  = (i / 24) & 63;
    int g  = i / (24 * 64);
    int k0 = kp * 2, k1 = kp * 2 + 1;
    float w0 = 0.f, w1 = 0.f;
    if (k0 < 36) { int tap = k0 >> 2, cg = k0 & 3; w0 = wt[((size_t)n * 64 + g * 4 + cg) * 9 + tap]; }
    if (k1 < 36) { int tap = k1 >> 2, cg = k1 & 3; w1 = wt[((size_t)n * 64 + g * 4 + cg) * 9 + tap]; }
    float h0 = bf16r(w0), h1 = bf16r(w1);
    g_dw_hi[i] = packbf2(h0, h1);
    g_dw_lo[i] = packbf2(w0 - h0, w1 - h1);
}

// =====================================================================
// conv3x3 implicit GEMM on tensor cores, double-buffered cp.async stage:
// prefetch cin-group g+1 during mma of group g.
// =====================================================================
#define SX_SZ (10*18*9)
#define SW_SZ (9*64*9)
#define SBUF  (2*SX_SZ + 2*SW_SZ)          // words per stage buffer (13608)
#define CONV_SMEM (2 * SBUF * 4)           // two stages

__device__ __forceinline__ void mma16816(float* d, const uint32_t* a, const uint32_t* b) {
    asm volatile(
        "mma.sync.aligned.m16n8k16.row.col.f32.bf16.bf16.f32 "
        "{%0,%1,%2,%3}, {%4,%5,%6,%7}, {%8,%9}, {%0,%1,%2,%3};\n"
        : "+f"(d[0]), "+f"(d[1]), "+f"(d[2]), "+f"(d[3])
        : "r"(a[0]), "r"(a[1]), "r"(a[2]), "r"(a[3]), "r"(b[0]), "r"(b[1]));
}
__device__ __forceinline__ void cpa4(uint32_t sa, const uint32_t* src) {
    asm volatile("cp.async.ca.shared.global [%0], [%1], 4;" :: "r"(sa), "l"(src));
}
__device__ __forceinline__ void cpa4z(uint32_t sa, const uint32_t* src) {
    asm volatile("cp.async.ca.shared.global [%0], [%1], 4, 0;" :: "r"(sa), "l"(src));
}

__global__ __launch_bounds__(256)
void conv_mma_k(int in_sel, int CPin, int w_sel,
                const float* __restrict__ bias, int out_sel,
                int CoutPad, int CoutReal, int mode, const float* __restrict__ flow)
{
    extern __shared__ uint32_t smem[];

    const uint32_t* in_hi = xbuf_hi(in_sel);
    const uint32_t* in_lo = xbuf_lo(in_sel);
    const uint32_t* w_hi  = wbuf(w_sel, 0);
    const uint32_t* w_lo  = wbuf(w_sel, 1);

    const int tid  = threadIdx.x;
    const int lane = tid & 31;
    const int wid  = tid >> 5;
    const int warp_m = wid & 1;
    const int warp_n = wid >> 1;
    const int r = lane >> 2;
    const int q = lane & 3;

    const int tx0 = blockIdx.x * 16;
    const int by  = blockIdx.y;
    const int b   = by >> 4;
    const int ty0 = (by & 15) * 8;
    const int oc0 = blockIdx.z * 64;

    const uint32_t smem_b = (uint32_t)__cvta_generic_to_shared(smem);

    float acc[4][2][4];
#pragma unroll
    for (int t = 0; t < 4; t++)
#pragma unroll
        for (int nt = 0; nt < 2; nt++)
#pragma unroll
            for (int i = 0; i < 4; i++) acc[t][nt][i] = 0.f;

    const int nG = (CPin + 7) / 8;

    // ---- stage one cin-group into buffer `buf` and commit ----
    auto stage = [&](int g, int buf) {
        const uint32_t b0  = smem_b + (uint32_t)(buf * SBUF * 4);
        const uint32_t bxh = b0;
        const uint32_t bxl = b0 + SX_SZ * 4;
        const uint32_t bwh = b0 + 2 * SX_SZ * 4;
        const uint32_t bwl = bwh + SW_SZ * 4;
        // input patch
        for (int i = tid; i < 8 * 180; i += 256) {
            int kp = i / 180;
            int pe = i - kp * 180;
            int rr = pe / 18, cl = pe - rr * 18;
            int gy = ty0 + rr - 1, gx = tx0 + cl - 1;
            int cp = g * 8 + kp;
            bool ok = ((unsigned)gy < HH) & ((unsigned)gx < WW) & (cp < CPin);
            int cpc = min(cp, CPin - 1);
            size_t gi = ((size_t)b * CPin + cpc) * HW + (ok ? gy * WW + gx : 0);
            uint32_t off = (uint32_t)(((rr * 18 + cl) * 9 + kp) * 4);
            if (ok) { cpa4 (bxh + off, in_hi + gi); cpa4 (bxl + off, in_lo + gi); }
            else    { cpa4z(bxh + off, in_hi + gi); cpa4z(bxl + off, in_lo + gi); }
        }
        // weights
        const uint32_t* whg = w_hi + (size_t)g * 9 * CoutPad * 8;
        const uint32_t* wlg = w_lo + (size_t)g * 9 * CoutPad * 8;
        for (int i = tid; i < 4608; i += 256) {
            int kp  = i & 7;
            int n   = (i >> 3) & 63;
            int tap = i >> 9;
            size_t gi = ((size_t)tap * CoutPad + oc0 + n) * 8 + kp;
            uint32_t off = (uint32_t)(((tap * 64 + n) * 9 + kp) * 4);
            cpa4(bwh + off, whg + gi);
            cpa4(bwl + off, wlg + gi);
        }
        asm volatile("cp.async.commit_group;" ::: "memory");
    };

    stage(0, 0);

    for (int g = 0; g < nG; g++) {
        const int buf = g & 1;
        if (g + 1 < nG) {
            stage(g + 1, buf ^ 1);
            asm volatile("cp.async.wait_group 1;" ::: "memory");
        } else {
            asm volatile("cp.async.wait_group 0;" ::: "memory");
        }
        __syncthreads();

        const uint32_t* s_xh = smem + buf * SBUF;
        const uint32_t* s_xl = s_xh + SX_SZ;
        const uint32_t* s_wh = s_xl + SX_SZ;
        const uint32_t* s_wl = s_wh + SW_SZ;

#pragma unroll
        for (int tap = 0; tap < 9; tap++) {
            const int dy = tap / 3, dx = tap % 3;
            uint32_t Ah[4][4], Al[4][4];
#pragma unroll
            for (int t = 0; t < 4; t++) {
                int ph = warp_m * 4 + t;
                int rowb = (ph + dy) * 18;
                int i00 = (rowb + r + dx) * 9 + q;
                int i10 = (rowb + r + 8 + dx) * 9 + q;
                Ah[t][0] = s_xh[i00];
                Ah[t][1] = s_xh[i10];
                Ah[t][2] = s_xh[i00 + 4];
                Ah[t][3] = s_xh[i10 + 4];
                Al[t][0] = s_xl[i00];
                Al[t][1] = s_xl[i10];
                Al[t][2] = s_xl[i00 + 4];
                Al[t][3] = s_xl[i10 + 4];
            }
            uint32_t Bh[2][2], Bl[2][2];
#pragma unroll
            for (int nt = 0; nt < 2; nt++) {
                int n = warp_n * 16 + nt * 8 + r;
                int iw = (tap * 64 + n) * 9 + q;
                Bh[nt][0] = s_wh[iw];
                Bh[nt][1] = s_wh[iw + 4];
                Bl[nt][0] = s_wl[iw];
                Bl[nt][1] = s_wl[iw + 4];
            }
#pragma unroll
            for (int t = 0; t < 4; t++)
#pragma unroll
                for (int nt = 0; nt < 2; nt++) {
                    mma16816(acc[t][nt], Ah[t], Bh[nt]);
                    mma16816(acc[t][nt], Ah[t], Bl[nt]);
                    mma16816(acc[t][nt], Al[t], Bh[nt]);
                }
        }
        __syncthreads();   // all warps done reading buf before it is restaged
    }

    if (mode == 1) {
        uint32_t* oh = xbuf_hi(out_sel);
        uint32_t* ol = xbuf_lo(out_sel);
#pragma unroll
        for (int t = 0; t < 4; t++) {
            int y = ty0 + warp_m * 4 + t;
#pragma unroll
            for (int nt = 0; nt < 2; nt++) {
                int ocb = warp_n * 16 + nt * 8 + 2 * q;
                float bv0 = bias[ocb], bv1 = bias[ocb + 1];
                int cp = (ocb >> 1);
#pragma unroll
                for (int half = 0; half < 2; half++) {
                    int x = tx0 + r + half * 8;
                    float v0 = acc[t][nt][half * 2 + 0] + bv0;
                    float v1 = acc[t][nt][half * 2 + 1] + bv1;
                    v0 = (v0 >= 0.f) ? v0 : 0.1f * v0;
                    v1 = (v1 >= 0.f) ? v1 : 0.1f * v1;
                    float h0 = bf16r(v0), h1 = bf16r(v1);
                    size_t oi = ((size_t)b * 32 + cp) * HW + y * WW + x;
                    oh[oi] = packbf2(h0, h1);
                    ol[oi] = packbf2(v0 - h0, v1 - h1);
                }
            }
        }
    } else {
#pragma unroll
        for (int t = 0; t < 4; t++) {
            int y = ty0 + warp_m * 4 + t;
#pragma unroll
            for (int nt = 0; nt < 2; nt++) {
                int ocb = oc0 + warp_n * 16 + nt * 8 + 2 * q;
#pragma unroll
                for (int half = 0; half < 2; half++) {
                    int x = tx0 + r + half * 8;
#pragma unroll
                    for (int e = 0; e < 2; e++) {
                        int oc = ocb + e;
                        if (oc >= CoutReal) continue;
                        float v = acc[t][nt][half * 2 + e] + bias[oc];
                        if (oc < 288) {
                            float fa = flow[((size_t)b * 2 + ((oc & 1) ? 0 : 1)) * HW + y * WW + x];
                            v = 10.f * tanhf(v) + fa;
                        } else {
                            v = 1.f / (1.f + expf(-v));
                        }
                        g_om[((size_t)b * 432 + oc) * HW + y * WW + x] = v;
                    }
                }
            }
        }
    }
}

// =====================================================================
// deformable conv as grouped mma (unchanged from passing R11)
// =====================================================================
__global__ __launch_bounds__(256)
void deform_mma_k(const float* __restrict__ x,
                  const float* __restrict__ bias,
                  float* __restrict__ out)
{
    __shared__ uint32_t ds[9600];
    uint32_t* s_ah = ds;              // 128*25
    uint32_t* s_al = ds + 3200;       // 128*25
    uint32_t* s_bh = ds + 6400;       // 64*25
    uint32_t* s_bl = ds + 8000;       // 64*25
    float*    s_out = (float*)ds;     // 64*130 (reused after mma)

    const int tid  = threadIdx.x;
    const int lane = tid & 31;
    const int wid  = tid >> 5;
    const int r = lane >> 2;
    const int q = lane & 3;

    const int blk = blockIdx.x;
    const int b   = blk >> 7;             // 128 blocks per batch
    const int p0  = (blk & 127) * 128;

    // zero A (covers the kp 18..23 pads; real kp rewritten every group)
    for (int i = tid; i < 6400; i += 256) ds[i] = 0;

    float acc[8][4];
#pragma unroll
    for (int nt = 0; nt < 8; nt++)
#pragma unroll
        for (int i = 0; i < 4; i++) acc[nt][i] = 0.f;

    const float* omb = g_om + (size_t)b * 432 * HW;

    for (int g = 0; g < 16; g++) {
        __syncthreads();

        // ---- load B: [64][24] -> [64][25] ----
        for (int i = tid; i < 1536; i += 256) {
            int n = i / 24, kp = i - n * 24;
            size_t gi = ((size_t)g * 64 + n) * 24 + kp;
            s_bh[n * 25 + kp] = g_dw_hi[gi];
            s_bl[n * 25 + kp] = g_dw_lo[gi];
        }

        // ---- gather A: tasks = tap*128 + pixel ----
        const float* xb = x + ((size_t)b * 64 + g * 4) * HW;
        for (int i = tid; i < 1152; i += 256) {
            int pix = i & 127, tap = i >> 7;
            int p = p0 + pix;
            int h = p >> 7, w = p & 127;
            int ch = g * 9 + tap;
            float dy = omb[(size_t)(2 * ch)     * HW + p];
            float dx = omb[(size_t)(2 * ch + 1) * HW + p];
            float m  = omb[(size_t)(288 + ch)   * HW + p];

            float pyf = (float)(h - 1 + tap / 3) + dy;
            float pxf = (float)(w - 1 + tap % 3) + dx;
            float y0f = floorf(pyf), x0f = floorf(pxf);
            int y0 = (int)y0f, x0 = (int)x0f;
            float wy = pyf - y0f, wx = pxf - x0f;

            float w00 = (1.f - wy) * (1.f - wx);
            float w01 = (1.f - wy) * wx;
            float w10 = wy * (1.f - wx);
            float w11 = wy * wx;

            bool v0 = (y0 >= 0) && (y0 < HH);
            bool v1 = (y0 + 1 >= 0) && (y0 + 1 < HH);
            bool u0 = (x0 >= 0) && (x0 < WW);
            bool u1 = (x0 + 1 >= 0) && (x0 + 1 < WW);
            float f00 = (v0 && u0) ? w00 * m : 0.f;
            float f01 = (v0 && u1) ? w01 * m : 0.f;
            float f10 = (v1 && u0) ? w10 * m : 0.f;
            float f11 = (v1 && u1) ? w11 * m : 0.f;

            int yc0 = min(max(y0, 0), HH - 1);
            int yc1 = min(max(y0 + 1, 0), HH - 1);
            int xc0 = min(max(x0, 0), WW - 1);
            int xc1 = min(max(x0 + 1, 0), WW - 1);
            int i00 = yc0 * WW + xc0, i01 = yc0 * WW + xc1;
            int i10 = yc1 * WW + xc0, i11 = yc1 * WW + xc1;

            float v[4];
#pragma unroll
            for (int cg = 0; cg < 4; cg++) {
                const float* xc = xb + cg * HW;
                v[cg] = f00 * xc[i00] + f01 * xc[i01]
                      + f10 * xc[i10] + f11 * xc[i11];
            }
            float h0 = bf16r(v[0]), h1 = bf16r(v[1]);
            float h2 = bf16r(v[2]), h3 = bf16r(v[3]);
            int base = pix * 25 + tap * 2;
            s_ah[base]     = packbf2(h0, h1);
            s_ah[base + 1] = packbf2(h2, h3);
            s_al[base]     = packbf2(v[0] - h0, v[1] - h1);
            s_al[base + 1] = packbf2(v[2] - h2, v[3] - h3);
        }
        __syncthreads();

        // ---- mma: warp owns pixels [wid*16, wid*16+16) x all 64 couts ----
        const int arow = (wid * 16 + r) * 25;
#pragma unroll
        for (int s = 0; s < 3; s++) {
            uint32_t Ah[4], Al[4];
            int ai = arow + s * 8 + q;
            Ah[0] = s_ah[ai];       Ah[1] = s_ah[ai + 200];
            Ah[2] = s_ah[ai + 4];   Ah[3] = s_ah[ai + 204];
            Al[0] = s_al[ai];       Al[1] = s_al[ai + 200];
            Al[2] = s_al[ai + 4];   Al[3] = s_al[ai + 204];
#pragma unroll
            for (int nt = 0; nt < 8; nt++) {
                uint32_t Bh[2], Bl[2];
                int bi = (nt * 8 + r) * 25 + s * 8 + q;
                Bh[0] = s_bh[bi]; Bh[1] = s_bh[bi + 4];
                Bl[0] = s_bl[bi]; Bl[1] = s_bl[bi + 4];
                mma16816(acc[nt], Ah, Bh);
                mma16816(acc[nt], Ah, Bl);
                mma16816(acc[nt], Al, Bh);
            }
        }
    }

    // ---- epilogue: transpose via smem, coalesced stores ----
    __syncthreads();
#pragma unroll
    for (int nt = 0; nt < 8; nt++)
#pragma unroll
        for (int half = 0; half < 2; half++)
#pragma unroll
            for (int e = 0; e < 2; e++) {
                int o   = nt * 8 + 2 * q + e;
                int pix = wid * 16 + r + half * 8;
                s_out[o * 130 + pix] = acc[nt][half * 2 + e];
            }
    __syncthreads();
    for (int i = tid; i < 8192; i += 256) {
        int o = i >> 7, j = i & 127;
        out[((size_t)b * 64 + o) * HW + p0 + j] = s_out[o * 130 + j] + bias[o];
    }
}

// =====================================================================
extern "C" void kernel_launch(void* const* d_in, const int* in_sizes, int n_in,
                              void* d_out, int out_size)
{
    const float* x    = (const float*)d_in[0];
    const float* xfw  = (const float*)d_in[1];
    const float* xcur = (const float*)d_in[2];
    const float* flow = (const float*)d_in[3];
    const float* w1   = (const float*)d_in[4];
    const float* b1   = (const float*)d_in[5];
    const float* w2   = (const float*)d_in[6];
    const float* b2   = (const float*)d_in[7];
    const float* w3   = (const float*)d_in[8];
    const float* b3   = (const float*)d_in[9];
    const float* w4   = (const float*)d_in[10];
    const float* b4   = (const float*)d_in[11];
    const float* wdc  = (const float*)d_in[12];
    const float* bdc  = (const float*)d_in[13];

    cudaFuncSetAttribute(conv_mma_k,
                         cudaFuncAttributeMaxDynamicSharedMemorySize, CONV_SMEM);

    // prep: input pairs + weight conversion
    prep_in_k<<<(BATCH * 65 * HW + 255) / 256, 256>>>(xfw, xcur, flow);
    prep_w_k<<<(9 * 9 * 64  * 8 + 255) / 256, 256>>>(w1, 130, 64,  64,  9, 1);
    prep_w_k<<<(4 * 9 * 64  * 8 + 255) / 256, 256>>>(w2,  64, 64,  64,  4, 2);
    prep_w_k<<<(4 * 9 * 64  * 8 + 255) / 256, 256>>>(w3,  64, 64,  64,  4, 3);
    prep_w_k<<<(4 * 9 * 448 * 8 + 255) / 256, 256>>>(w4,  64, 448, 432, 4, 4);
    prep_dw_k<<<(16 * 64 * 24 + 255) / 256, 256>>>(wdc);

    dim3 gridA(8, 16 * BATCH, 1);
    conv_mma_k<<<gridA, 256, CONV_SMEM>>>(0, 65, 1, b1, 1, 64, 64, 1, nullptr);
    conv_mma_k<<<gridA, 256, CONV_SMEM>>>(1, 32, 2, b2, 2, 64, 64, 1, nullptr);
    conv_mma_k<<<gridA, 256, CONV_SMEM>>>(2, 32, 3, b3, 1, 64, 64, 1, nullptr);
    dim3 gridB(8, 16 * BATCH, 7);
    conv_mma_k<<<gridB, 256, CONV_SMEM>>>(1, 32, 4, b4, 0, 448, 432, 2, flow);

    deform_mma_k<<<BATCH * HW / 128, 256>>>(x, bdc, (float*)d_out);
}

// round 15
// speedup vs baseline: 1.0182x; 1.0182x over previous
#include <cuda_runtime.h>
#include <cuda_bf16.h>
#include <math.h>
#include <stdint.h>

#define BATCH 4
#define HH 128
#define WW 128
#define HW (HH*WW)

// ---- scratch (static device globals; no allocation allowed) ----
// packed bf16x2 channel-pair planes (word cp = channels 2cp,2cp+1)
__device__ uint32_t g_xin_hi[BATCH*65*HW], g_xin_lo[BATCH*65*HW];  // conv1 input (65 pairs)
__device__ uint32_t g_hA_hi [BATCH*32*HW], g_hA_lo [BATCH*32*HW];
__device__ uint32_t g_hB_hi [BATCH*32*HW], g_hB_lo [BATCH*32*HW];
__device__ float    g_om[BATCH*432*HW];   // conv4 out: offsets+mask (fp32 for deform)
// pre-converted weights, layout [g][tap][coutPad][kp]
__device__ uint32_t g_w1_hi[9*9*64*8],  g_w1_lo[9*9*64*8];
__device__ uint32_t g_w2_hi[4*9*64*8],  g_w2_lo[4*9*64*8];
__device__ uint32_t g_w3_hi[4*9*64*8],  g_w3_lo[4*9*64*8];
__device__ uint32_t g_w4_hi[4*9*448*8], g_w4_lo[4*9*448*8];
// deform weights: [g][cout 64][kp 24] (k = tap*4+cg, 36 real -> 48 padded)
__device__ uint32_t g_dw_hi[16*64*24], g_dw_lo[16*64*24];

__device__ __forceinline__ uint32_t* xbuf_hi(int i) {
    switch (i) { case 0: return g_xin_hi; case 1: return g_hA_hi; default: return g_hB_hi; }
}
__device__ __forceinline__ uint32_t* xbuf_lo(int i) {
    switch (i) { case 0: return g_xin_lo; case 1: return g_hA_lo; default: return g_hB_lo; }
}
__device__ __forceinline__ uint32_t* wbuf(int i, int lo) {
    switch (i) {
        case 1: return lo ? g_w1_lo : g_w1_hi;
        case 2: return lo ? g_w2_lo : g_w2_hi;
        case 3: return lo ? g_w3_lo : g_w3_hi;
        default: return lo ? g_w4_lo : g_w4_hi;
    }
}

__device__ __forceinline__ uint32_t packbf2(float a, float b) {
    __nv_bfloat162 h = __floats2bfloat162_rn(a, b);
    return *reinterpret_cast<uint32_t*>(&h);
}
__device__ __forceinline__ float bf16r(float v) {
    return __bfloat162float(__float2bfloat16_rn(v));
}

// =====================================================================
// prep kernels (tiny, run once per launch inside the graph)
// =====================================================================
__global__ void prep_in_k(const float* __restrict__ xfw,
                          const float* __restrict__ xc,
                          const float* __restrict__ fl)
{
    int i = blockIdx.x * 256 + threadIdx.x;
    const int total = BATCH * 65 * HW;
    if (i >= total) return;
    int b  = i / (65 * HW);
    int r  = i - b * 65 * HW;
    int cp = r / HW;
    int sp = r - cp * HW;
    float v0, v1;
    if (cp < 32) {
        const float* s = xfw + ((size_t)b * 64 + 2 * cp) * HW + sp;
        v0 = s[0]; v1 = s[HW];
    } else if (cp < 64) {
        const float* s = xc + ((size_t)b * 64 + 2 * (cp - 32)) * HW + sp;
        v0 = s[0]; v1 = s[HW];
    } else {
        const float* s = fl + (size_t)b * 2 * HW + sp;
        v0 = s[0]; v1 = s[HW];
    }
    float h0 = bf16r(v0), h1 = bf16r(v1);
    g_xin_hi[i] = packbf2(h0, h1);
    g_xin_lo[i] = packbf2(v0 - h0, v1 - h1);
}

__global__ void prep_w_k(const float* __restrict__ wt,
                         int CinR, int CoutPad, int CoutReal, int nG, int wsel)
{
    int i = blockIdx.x * 256 + threadIdx.x;
    const int total = nG * 9 * CoutPad * 8;
    if (i >= total) return;
    int kp  = i & 7;
    int n   = (i >> 3) % CoutPad;
    int tap = ((i >> 3) / CoutPad) % 9;
    int g   = i / (9 * CoutPad * 8);
    int cin = g * 16 + kp * 2;
    float w0 = 0.f, w1 = 0.f;
    if (n < CoutReal) {
        if (cin     < CinR) w0 = wt[((size_t)n * CinR + cin    ) * 9 + tap];
        if (cin + 1 < CinR) w1 = wt[((size_t)n * CinR + cin + 1) * 9 + tap];
    }
    float h0 = bf16r(w0), h1 = bf16r(w1);
    wbuf(wsel, 0)[i] = packbf2(h0, h1);
    wbuf(wsel, 1)[i] = packbf2(w0 - h0, w1 - h1);
}

// deform weights: k-index = tap*4 + cg; kp pairs (0..17 real, 18..23 zero)
__global__ void prep_dw_k(const float* __restrict__ wt)
{
    int i = blockIdx.x * 256 + threadIdx.x;
    if (i >= 16 * 64 * 24) return;
    int kp = i % 24;
    int n  = (i / 24) & 63;
    int g  = i / (24 * 64);
    int k0 = kp * 2, k1 = kp * 2 + 1;
    float w0 = 0.f, w1 = 0.f;
    if (k0 < 36) { int tap = k0 >> 2, cg = k0 & 3; w0 = wt[((size_t)n * 64 + g * 4 + cg) * 9 + tap]; }
    if (k1 < 36) { int tap = k1 >> 2, cg = k1 & 3; w1 = wt[((size_t)n * 64 + g * 4 + cg) * 9 + tap]; }
    float h0 = bf16r(w0), h1 = bf16r(w1);
    g_dw_hi[i] = packbf2(h0, h1);
    g_dw_lo[i] = packbf2(w0 - h0, w1 - h1);
}

// =====================================================================
// conv3x3 implicit GEMM on tensor cores.  Single-stage smem (double
// buffer proved neutral -> staging is ISSUE-bound, not latency-bound).
// Weights staged via 16B cp.async into stride-12 rows (4x fewer ops).
// =====================================================================
#define SX_SZ (10*18*9)
#define SW_STRIDE 12
#define SW_SZ (9*64*SW_STRIDE)
#define CONV_SMEM ((2*SX_SZ + 2*SW_SZ) * 4)

__device__ __forceinline__ void mma16816(float* d, const uint32_t* a, const uint32_t* b) {
    asm volatile(
        "mma.sync.aligned.m16n8k16.row.col.f32.bf16.bf16.f32 "
        "{%0,%1,%2,%3}, {%4,%5,%6,%7}, {%8,%9}, {%0,%1,%2,%3};\n"
        : "+f"(d[0]), "+f"(d[1]), "+f"(d[2]), "+f"(d[3])
        : "r"(a[0]), "r"(a[1]), "r"(a[2]), "r"(a[3]), "r"(b[0]), "r"(b[1]));
}
__device__ __forceinline__ void cpa4(uint32_t sa, const uint32_t* src) {
    asm volatile("cp.async.ca.shared.global [%0], [%1], 4;" :: "r"(sa), "l"(src));
}
__device__ __forceinline__ void cpa4z(uint32_t sa, const uint32_t* src) {
    asm volatile("cp.async.ca.shared.global [%0], [%1], 4, 0;" :: "r"(sa), "l"(src));
}
__device__ __forceinline__ void cpa16(uint32_t sa, const uint32_t* src) {
    asm volatile("cp.async.cg.shared.global [%0], [%1], 16;" :: "r"(sa), "l"(src));
}

__global__ __launch_bounds__(256)
void conv_mma_k(int in_sel, int CPin, int w_sel,
                const float* __restrict__ bias, int out_sel,
                int CoutPad, int CoutReal, int mode, const float* __restrict__ flow)
{
    extern __shared__ uint32_t smem[];
    uint32_t* s_xh = smem;
    uint32_t* s_xl = s_xh + SX_SZ;
    uint32_t* s_wh = s_xl + SX_SZ;
    uint32_t* s_wl = s_wh + SW_SZ;

    const uint32_t* in_hi = xbuf_hi(in_sel);
    const uint32_t* in_lo = xbuf_lo(in_sel);
    const uint32_t* w_hi  = wbuf(w_sel, 0);
    const uint32_t* w_lo  = wbuf(w_sel, 1);

    const int tid  = threadIdx.x;
    const int lane = tid & 31;
    const int wid  = tid >> 5;
    const int warp_m = wid & 1;
    const int warp_n = wid >> 1;
    const int r = lane >> 2;
    const int q = lane & 3;

    const int tx0 = blockIdx.x * 16;
    const int by  = blockIdx.y;
    const int b   = by >> 4;
    const int ty0 = (by & 15) * 8;
    const int oc0 = blockIdx.z * 64;

    const uint32_t sxh_b = (uint32_t)__cvta_generic_to_shared(s_xh);
    const uint32_t sxl_b = (uint32_t)__cvta_generic_to_shared(s_xl);
    const uint32_t swh_b = (uint32_t)__cvta_generic_to_shared(s_wh);
    const uint32_t swl_b = (uint32_t)__cvta_generic_to_shared(s_wl);

    float acc[4][2][4];
#pragma unroll
    for (int t = 0; t < 4; t++)
#pragma unroll
        for (int nt = 0; nt < 2; nt++)
#pragma unroll
            for (int i = 0; i < 4; i++) acc[t][nt][i] = 0.f;

    const int nG = (CPin + 7) / 8;

    for (int g = 0; g < nG; g++) {
        __syncthreads();   // previous iteration's readers done

        // ---- stage input patch (4B gathers; kp plane-major in gmem) ----
        for (int i = tid; i < 8 * 180; i += 256) {
            int kp = i / 180;
            int pe = i - kp * 180;
            int rr = pe / 18, cl = pe - rr * 18;
            int gy = ty0 + rr - 1, gx = tx0 + cl - 1;
            int cp = g * 8 + kp;
            bool ok = ((unsigned)gy < HH) & ((unsigned)gx < WW) & (cp < CPin);
            int cpc = min(cp, CPin - 1);
            size_t gi = ((size_t)b * CPin + cpc) * HW + (ok ? gy * WW + gx : 0);
            uint32_t off = (uint32_t)(((rr * 18 + cl) * 9 + kp) * 4);
            if (ok) { cpa4 (sxh_b + off, in_hi + gi); cpa4 (sxl_b + off, in_lo + gi); }
            else    { cpa4z(sxh_b + off, in_hi + gi); cpa4z(sxl_b + off, in_lo + gi); }
        }
        // ---- stage weights: 16B copies, stride-12 rows ----
        {
            const uint32_t* whg = w_hi + (size_t)g * 9 * CoutPad * 8;
            const uint32_t* wlg = w_lo + (size_t)g * 9 * CoutPad * 8;
            // 9 taps x 64 n x 2 chunks = 1152 transfers per plane
            for (int i = tid; i < 1152; i += 256) {
                int chunk = i & 1;
                int n     = (i >> 1) & 63;
                int tap   = i >> 7;
                size_t gi = ((size_t)tap * CoutPad + oc0 + n) * 8 + chunk * 4;
                uint32_t off = (uint32_t)(((tap * 64 + n) * SW_STRIDE + chunk * 4) * 4);
                cpa16(swh_b + off, whg + gi);
                cpa16(swl_b + off, wlg + gi);
            }
        }
        asm volatile("cp.async.commit_group;" ::: "memory");
        asm volatile("cp.async.wait_group 0;" ::: "memory");
        __syncthreads();

        // ---- 9 taps of mma ----
#pragma unroll
        for (int tap = 0; tap < 9; tap++) {
            const int dy = tap / 3, dx = tap % 3;
            uint32_t Ah[4][4], Al[4][4];
#pragma unroll
            for (int t = 0; t < 4; t++) {
                int ph = warp_m * 4 + t;
                int rowb = (ph + dy) * 18;
                int i00 = (rowb + r + dx) * 9 + q;
                int i10 = (rowb + r + 8 + dx) * 9 + q;
                Ah[t][0] = s_xh[i00];
                Ah[t][1] = s_xh[i10];
                Ah[t][2] = s_xh[i00 + 4];
                Ah[t][3] = s_xh[i10 + 4];
                Al[t][0] = s_xl[i00];
                Al[t][1] = s_xl[i10];
                Al[t][2] = s_xl[i00 + 4];
                Al[t][3] = s_xl[i10 + 4];
            }
            uint32_t Bh[2][2], Bl[2][2];
#pragma unroll
            for (int nt = 0; nt < 2; nt++) {
                int n = warp_n * 16 + nt * 8 + r;
                int iw = (tap * 64 + n) * SW_STRIDE + q;
                Bh[nt][0] = s_wh[iw];
                Bh[nt][1] = s_wh[iw + 4];
                Bl[nt][0] = s_wl[iw];
                Bl[nt][1] = s_wl[iw + 4];
            }
#pragma unroll
            for (int t = 0; t < 4; t++)
#pragma unroll
                for (int nt = 0; nt < 2; nt++) {
                    mma16816(acc[t][nt], Ah[t], Bh[nt]);
                    mma16816(acc[t][nt], Ah[t], Bl[nt]);
                    mma16816(acc[t][nt], Al[t], Bh[nt]);
                }
        }
    }

    if (mode == 1) {
        uint32_t* oh = xbuf_hi(out_sel);
        uint32_t* ol = xbuf_lo(out_sel);
#pragma unroll
        for (int t = 0; t < 4; t++) {
            int y = ty0 + warp_m * 4 + t;
#pragma unroll
            for (int nt = 0; nt < 2; nt++) {
                int ocb = warp_n * 16 + nt * 8 + 2 * q;
                float bv0 = bias[ocb], bv1 = bias[ocb + 1];
                int cp = (ocb >> 1);
#pragma unroll
                for (int half = 0; half < 2; half++) {
                    int x = tx0 + r + half * 8;
                    float v0 = acc[t][nt][half * 2 + 0] + bv0;
                    float v1 = acc[t][nt][half * 2 + 1] + bv1;
                    v0 = (v0 >= 0.f) ? v0 : 0.1f * v0;
                    v1 = (v1 >= 0.f) ? v1 : 0.1f * v1;
                    float h0 = bf16r(v0), h1 = bf16r(v1);
                    size_t oi = ((size_t)b * 32 + cp) * HW + y * WW + x;
                    oh[oi] = packbf2(h0, h1);
                    ol[oi] = packbf2(v0 - h0, v1 - h1);
                }
            }
        }
    } else {
#pragma unroll
        for (int t = 0; t < 4; t++) {
            int y = ty0 + warp_m * 4 + t;
#pragma unroll
            for (int nt = 0; nt < 2; nt++) {
                int ocb = oc0 + warp_n * 16 + nt * 8 + 2 * q;
#pragma unroll
                for (int half = 0; half < 2; half++) {
                    int x = tx0 + r + half * 8;
#pragma unroll
                    for (int e = 0; e < 2; e++) {
                        int oc = ocb + e;
                        if (oc >= CoutReal) continue;
                        float v = acc[t][nt][half * 2 + e] + bias[oc];
                        if (oc < 288) {
                            float fa = flow[((size_t)b * 2 + ((oc & 1) ? 0 : 1)) * HW + y * WW + x];
                            v = 10.f * tanhf(v) + fa;
                        } else {
                            v = 1.f / (1.f + expf(-v));
                        }
                        g_om[((size_t)b * 432 + oc) * HW + y * WW + x] = v;
                    }
                }
            }
        }
    }
}

// =====================================================================
// deformable conv as grouped mma (unchanged from passing R11)
// =====================================================================
__global__ __launch_bounds__(256)
void deform_mma_k(const float* __restrict__ x,
                  const float* __restrict__ bias,
                  float* __restrict__ out)
{
    __shared__ uint32_t ds[9600];
    uint32_t* s_ah = ds;              // 128*25
    uint32_t* s_al = ds + 3200;       // 128*25
    uint32_t* s_bh = ds + 6400;       // 64*25
    uint32_t* s_bl = ds + 8000;       // 64*25
    float*    s_out = (float*)ds;     // 64*130 (reused after mma)

    const int tid  = threadIdx.x;
    const int lane = tid & 31;
    const int wid  = tid >> 5;
    const int r = lane >> 2;
    const int q = lane & 3;

    const int blk = blockIdx.x;
    const int b   = blk >> 7;             // 128 blocks per batch
    const int p0  = (blk & 127) * 128;

    // zero A (covers the kp 18..23 pads; real kp rewritten every group)
    for (int i = tid; i < 6400; i += 256) ds[i] = 0;

    float acc[8][4];
#pragma unroll
    for (int nt = 0; nt < 8; nt++)
#pragma unroll
        for (int i = 0; i < 4; i++) acc[nt][i] = 0.f;

    const float* omb = g_om + (size_t)b * 432 * HW;

    for (int g = 0; g < 16; g++) {
        __syncthreads();

        // ---- load B: [64][24] -> [64][25] ----
        for (int i = tid; i < 1536; i += 256) {
            int n = i / 24, kp = i - n * 24;
            size_t gi = ((size_t)g * 64 + n) * 24 + kp;
            s_bh[n * 25 + kp] = g_dw_hi[gi];
            s_bl[n * 25 + kp] = g_dw_lo[gi];
        }

        // ---- gather A: tasks = tap*128 + pixel ----
        const float* xb = x + ((size_t)b * 64 + g * 4) * HW;
        for (int i = tid; i < 1152; i += 256) {
            int pix = i & 127, tap = i >> 7;
            int p = p0 + pix;
            int h = p >> 7, w = p & 127;
            int ch = g * 9 + tap;
            float dy = omb[(size_t)(2 * ch)     * HW + p];
            float dx = omb[(size_t)(2 * ch + 1) * HW + p];
            float m  = omb[(size_t)(288 + ch)   * HW + p];

            float pyf = (float)(h - 1 + tap / 3) + dy;
            float pxf = (float)(w - 1 + tap % 3) + dx;
            float y0f = floorf(pyf), x0f = floorf(pxf);
            int y0 = (int)y0f, x0 = (int)x0f;
            float wy = pyf - y0f, wx = pxf - x0f;

            float w00 = (1.f - wy) * (1.f - wx);
            float w01 = (1.f - wy) * wx;
            float w10 = wy * (1.f - wx);
            float w11 = wy * wx;

            bool v0 = (y0 >= 0) && (y0 < HH);
            bool v1 = (y0 + 1 >= 0) && (y0 + 1 < HH);
            bool u0 = (x0 >= 0) && (x0 < WW);
            bool u1 = (x0 + 1 >= 0) && (x0 + 1 < WW);
            float f00 = (v0 && u0) ? w00 * m : 0.f;
            float f01 = (v0 && u1) ? w01 * m : 0.f;
            float f10 = (v1 && u0) ? w10 * m : 0.f;
            float f11 = (v1 && u1) ? w11 * m : 0.f;

            int yc0 = min(max(y0, 0), HH - 1);
            int yc1 = min(max(y0 + 1, 0), HH - 1);
            int xc0 = min(max(x0, 0), WW - 1);
            int xc1 = min(max(x0 + 1, 0), WW - 1);
            int i00 = yc0 * WW + xc0, i01 = yc0 * WW + xc1;
            int i10 = yc1 * WW + xc0, i11 = yc1 * WW + xc1;

            float v[4];
#pragma unroll
            for (int cg = 0; cg < 4; cg++) {
                const float* xc = xb + cg * HW;
                v[cg] = f00 * xc[i00] + f01 * xc[i01]
                      + f10 * xc[i10] + f11 * xc[i11];
            }
            float h0 = bf16r(v[0]), h1 = bf16r(v[1]);
            float h2 = bf16r(v[2]), h3 = bf16r(v[3]);
            int base = pix * 25 + tap * 2;
            s_ah[base]     = packbf2(h0, h1);
            s_ah[base + 1] = packbf2(h2, h3);
            s_al[base]     = packbf2(v[0] - h0, v[1] - h1);
            s_al[base + 1] = packbf2(v[2] - h2, v[3] - h3);
        }
        __syncthreads();

        // ---- mma: warp owns pixels [wid*16, wid*16+16) x all 64 couts ----
        const int arow = (wid * 16 + r) * 25;
#pragma unroll
        for (int s = 0; s < 3; s++) {
            uint32_t Ah[4], Al[4];
            int ai = arow + s * 8 + q;
            Ah[0] = s_ah[ai];       Ah[1] = s_ah[ai + 200];
            Ah[2] = s_ah[ai + 4];   Ah[3] = s_ah[ai + 204];
            Al[0] = s_al[ai];       Al[1] = s_al[ai + 200];
            Al[2] = s_al[ai + 4];   Al[3] = s_al[ai + 204];
#pragma unroll
            for (int nt = 0; nt < 8; nt++) {
                uint32_t Bh[2], Bl[2];
                int bi = (nt * 8 + r) * 25 + s * 8 + q;
                Bh[0] = s_bh[bi]; Bh[1] = s_bh[bi + 4];
                Bl[0] = s_bl[bi]; Bl[1] = s_bl[bi + 4];
                mma16816(acc[nt], Ah, Bh);
                mma16816(acc[nt], Ah, Bl);
                mma16816(acc[nt], Al, Bh);
            }
        }
    }

    // ---- epilogue: transpose via smem, coalesced stores ----
    __syncthreads();
#pragma unroll
    for (int nt = 0; nt < 8; nt++)
#pragma unroll
        for (int half = 0; half < 2; half++)
#pragma unroll
            for (int e = 0; e < 2; e++) {
                int o   = nt * 8 + 2 * q + e;
                int pix = wid * 16 + r + half * 8;
                s_out[o * 130 + pix] = acc[nt][half * 2 + e];
            }
    __syncthreads();
    for (int i = tid; i < 8192; i += 256) {
        int o = i >> 7, j = i & 127;
        out[((size_t)b * 64 + o) * HW + p0 + j] = s_out[o * 130 + j] + bias[o];
    }
}

// =====================================================================
extern "C" void kernel_launch(void* const* d_in, const int* in_sizes, int n_in,
                              void* d_out, int out_size)
{
    const float* x    = (const float*)d_in[0];
    const float* xfw  = (const float*)d_in[1];
    const float* xcur = (const float*)d_in[2];
    const float* flow = (const float*)d_in[3];
    const float* w1   = (const float*)d_in[4];
    const float* b1   = (const float*)d_in[5];
    const float* w2   = (const float*)d_in[6];
    const float* b2   = (const float*)d_in[7];
    const float* w3   = (const float*)d_in[8];
    const float* b3   = (const float*)d_in[9];
    const float* w4   = (const float*)d_in[10];
    const float* b4   = (const float*)d_in[11];
    const float* wdc  = (const float*)d_in[12];
    const float* bdc  = (const float*)d_in[13];

    cudaFuncSetAttribute(conv_mma_k,
                         cudaFuncAttributeMaxDynamicSharedMemorySize, CONV_SMEM);

    // prep: input pairs + weight conversion
    prep_in_k<<<(BATCH * 65 * HW + 255) / 256, 256>>>(xfw, xcur, flow);
    prep_w_k<<<(9 * 9 * 64  * 8 + 255) / 256, 256>>>(w1, 130, 64,  64,  9, 1);
    prep_w_k<<<(4 * 9 * 64  * 8 + 255) / 256, 256>>>(w2,  64, 64,  64,  4, 2);
    prep_w_k<<<(4 * 9 * 64  * 8 + 255) / 256, 256>>>(w3,  64, 64,  64,  4, 3);
    prep_w_k<<<(4 * 9 * 448 * 8 + 255) / 256, 256>>>(w4,  64, 448, 432, 4, 4);
    prep_dw_k<<<(16 * 64 * 24 + 255) / 256, 256>>>(wdc);

    dim3 gridA(8, 16 * BATCH, 1);
    conv_mma_k<<<gridA, 256, CONV_SMEM>>>(0, 65, 1, b1, 1, 64, 64, 1, nullptr);
    conv_mma_k<<<gridA, 256, CONV_SMEM>>>(1, 32, 2, b2, 2, 64, 64, 1, nullptr);
    conv_mma_k<<<gridA, 256, CONV_SMEM>>>(2, 32, 3, b3, 1, 64, 64, 1, nullptr);
    dim3 gridB(8, 16 * BATCH, 7);
    conv_mma_k<<<gridB, 256, CONV_SMEM>>>(1, 32, 4, b4, 0, 448, 432, 2, flow);

    deform_mma_k<<<BATCH * HW / 128, 256>>>(x, bdc, (float*)d_out);
}